// round 12
// baseline (speedup 1.0000x reference)
#include <cuda_runtime.h>

// Fused depth-3 sliding-window path signature (Chen chunk factorization),
// j-split lanes for occupancy: each thread owns 3 of the 6 j-rows.
// B=256, L=2048, C=6, WIN=64, STRIDE=32 -> 63 windows / batch.
// Grid = 1792 blocks (batch = blk/7, group g = blk%7) x 128 threads.
// Scan lane (chunk mc, i, jh): state s1, T2[3] (=3*2*s2, j=3jh..3jh+2),
// S3[3][6] (=6*s3 rows j=3jh..3jh+2).  coef_j = a*d_j + T2[j] (1 FMA).
// Combine lane (window wl, i, jh): produces r2[3], r3[3][6] (rows 3jh..3jh+2).
// Output staged in smem [wl][258] then block-coalesced copy.

namespace {

constexpr int BATCH   = 256;
constexpr int LEN     = 2048;
constexpr int CH      = 6;
constexpr int NW      = 63;
constexpr int GROUPS  = 7;
constexpr int THREADS = 128;
constexpr int NCHUNKL = 10;               // chunks per block (1 overlap)
constexpr int NWL     = 9;                // windows per block (7*9 = 63 exact)
constexpr int NDXL    = 320;              // staged increments per block
constexpr int SROWD2  = 331;              // float2 row stride (320+10 pad, odd)
constexpr int NSCAN   = NCHUNKL * 12;     // 120 scan lanes (12 per chunk)
constexpr int SCOL    = 61;               // sig column stride (60 cols + pad)
constexpr int SM_FLOATS = 43 * SCOL;      // 2623 >= max(3*331*2=1986, 9*258=2322)

__global__ __launch_bounds__(THREADS, 12)
void fused_kernel(const float* __restrict__ path, float* __restrict__ out) {
    __shared__ __align__(16) float sm[SM_FLOATS];
    float2* __restrict__ s_dx2 = reinterpret_cast<float2*>(sm); // [3][SROWD2]
    float*  __restrict__ s_sig = sm;                            // [43][SCOL]

    const int tid = threadIdx.x;
    const int b   = blockIdx.x / GROUPS;
    const int g   = blockIdx.x - b * GROUPS;
    const int l0  = g * (NWL * 32);                 // 288 * g
    const float2* __restrict__ rowv =
        reinterpret_cast<const float2*>(path + (long long)b * (LEN * CH));

    // ---- stage increments as float2 (zero-fill global l >= 2047) ----
    for (int idx = tid; idx < NDXL * 3; idx += THREADS) {
        const int l  = idx / 3;
        const int pr = idx - l * 3;
        float2 d2 = make_float2(0.0f, 0.0f);
        const int gl = l0 + l;
        if (gl < LEN - 1) {
            const float2 v0 = rowv[gl * 3 + pr];
            const float2 v1 = rowv[gl * 3 + 3 + pr];
            d2.x = v1.x - v0.x;
            d2.y = v1.y - v0.y;
        }
        s_dx2[pr * SROWD2 + l + (l >> 5)] = d2;
    }
    __syncthreads();

    // lane decode: 12 threads per chunk = 6 channels x 2 j-halves
    const int mc  = tid / 12;          // chunk (scan) / window (combine)
    const int sub = tid - mc * 12;
    const int i   = sub >> 1;          // leading channel 0..5
    const int jh  = sub & 1;           // j-half: rows j0..j0+2
    const int j0  = 3 * jh;
    const bool scan_lane = (tid < NSCAN);
    const int col = mc * CH + i;       // s_sig column for this (chunk, i)

    float s1 = 0.0f;
    float T2[3];                       // 3*(2*s2[i][j]), j = j0..j0+2
    float S3[3][6];                    // 6*s3[i][j][k],  j = j0..j0+2
#pragma unroll
    for (int jj = 0; jj < 3; ++jj) {
        T2[jj] = 0.0f;
#pragma unroll
        for (int k = 0; k < 6; ++k) S3[jj][k] = 0.0f;
    }

    if (scan_lane) {
        const int base = 33 * mc;      // padded float2 offset of local l = 32*mc
        const float* __restrict__ rowi = sm + 2 * (i >> 1) * SROWD2 + (i & 1);

#pragma unroll 4
        for (int t = 0; t < 32; ++t) {
            const int off = base + t;
            const float2 d01 = s_dx2[0 * SROWD2 + off];
            const float2 d23 = s_dx2[1 * SROWD2 + off];
            const float2 d45 = s_dx2[2 * SROWD2 + off];
            const float di = rowi[2 * off];

            const float a   = fmaf(3.0f, s1, di);          // di + 3 s1 (old s1)
            const float b23 = fmaf(6.0f, s1, 3.0f * di);   // 3*(di + 2 s1)

            const float d[6] = {d01.x, d01.y, d23.x, d23.y, d45.x, d45.y};

            float coef[3];                                  // uses old T2
#pragma unroll
            for (int jj = 0; jj < 3; ++jj) coef[jj] = fmaf(a, d[j0 + jj], T2[jj]);

#pragma unroll
            for (int jj = 0; jj < 3; ++jj)
#pragma unroll
                for (int k = 0; k < 6; ++k)
                    S3[jj][k] = fmaf(coef[jj], d[k], S3[jj][k]);

#pragma unroll
            for (int jj = 0; jj < 3; ++jj) T2[jj] = fmaf(b23, d[j0 + jj], T2[jj]);
            s1 += di;
        }
    }

    // ---- snapshot d_last for local window wl = mc (local l' = 32mc+63) ----
    float dc[6];
    {
        const int off = 33 * mc + 64;
        const bool cwn = (mc < NWL);
        float2 c01 = make_float2(0.0f, 0.0f), c23 = c01, c45 = c01;
        if (cwn) {
            c01 = s_dx2[0 * SROWD2 + off];
            c23 = s_dx2[1 * SROWD2 + off];
            c45 = s_dx2[2 * SROWD2 + off];
        }
        dc[0] = c01.x; dc[1] = c01.y; dc[2] = c23.x;
        dc[3] = c23.y; dc[4] = c45.x; dc[5] = c45.y;
    }
    __syncthreads();   // all dx reads done before s_sig overwrites

    // ---- publish chunk state: S2 = T2/3, column = mc*6+i ----
    if (scan_lane) {
        if (jh == 0) s_sig[col] = s1;
        const float third = 1.0f / 3.0f;
#pragma unroll
        for (int jj = 0; jj < 3; ++jj)
            s_sig[(1 + j0 + jj) * SCOL + col] = T2[jj] * third;
#pragma unroll
        for (int jj = 0; jj < 3; ++jj)
#pragma unroll
            for (int k = 0; k < 6; ++k)
                s_sig[(7 + (j0 + jj) * 6 + k) * SCOL + col] = S3[jj][k];
    }
    __syncthreads();

    // ---- combine: window wl = mc (< 9), rows j = j0..j0+2 ----
    const bool cw = (mc < NWL);    // w = 9g + mc <= 62 < NW always

    float r1 = 0.0f, r2[3], r3[3][6];
    if (cw) {
        const int ca  = col;               // A_w lane i
        const int cb0 = (mc + 1) * CH;     // A_{w+1} lane base
        const int cbi = cb0 + i;

        const float a1 = s_sig[ca];
        float b1[6];
#pragma unroll
        for (int j = 0; j < 6; ++j) b1[j] = s_sig[cb0 + j];

        const float m1 = a1 + b1[i];

        // M2 row i (2x), own j rows: M2[jj] = A2[i][j] + B2[i][j] + 2 a1 b1[j]
        float A2r[3], M2[3];
#pragma unroll
        for (int jj = 0; jj < 3; ++jj) {
            const int j = j0 + jj;
            A2r[jj] = s_sig[(1 + j) * SCOL + ca];
            M2[jj]  = A2r[jj] + s_sig[(1 + j) * SCOL + cbi] + 2.0f * a1 * b1[j];
        }

        r1 = m1 - dc[i];

        const float c2 = dc[i] - 2.0f * m1;
#pragma unroll
        for (int jj = 0; jj < 3; ++jj) r2[jj] = fmaf(c2, dc[j0 + jj], M2[jj]);

        const float t3a1 = 3.0f * a1;
        const float c3   = 3.0f * m1 - dc[i];
#pragma unroll
        for (int jj = 0; jj < 3; ++jj) {
            const int j = j0 + jj;
            const float a2b  = 3.0f * A2r[jj];
            const float coef = fmaf(c3, dc[j], -3.0f * M2[jj]);
#pragma unroll
            for (int k = 0; k < 6; ++k) {
                float v = s_sig[(7 + j * 6 + k) * SCOL + ca]
                        + s_sig[(7 + j * 6 + k) * SCOL + cbi];
                v = fmaf(a2b, b1[k], v);
                v = fmaf(t3a1, s_sig[(1 + k) * SCOL + cb0 + j], v);  // 3 a1 B2[j][k]
                r3[jj][k] = fmaf(coef, dc[k], v);
            }
        }
    }
    __syncthreads();   // all s_sig reads done before output staging overwrites

    // ---- stage output in smem as [wl][258] ----
    if (cw) {
        float* __restrict__ so = sm + mc * 258;
        if (jh == 0) so[i] = r1;
#pragma unroll
        for (int jj = 0; jj < 3; ++jj) so[6 + i * 6 + j0 + jj] = r2[jj];
#pragma unroll
        for (int jj = 0; jj < 3; ++jj)
#pragma unroll
            for (int k = 0; k < 6; ++k)
                so[42 + i * 36 + (j0 + jj) * 6 + k] = r3[jj][k];
    }
    __syncthreads();

    // ---- coalesced copy to global (all blocks identical: 9 windows) ----
    constexpr int CNT = NWL * 258;       // 2322
    float* __restrict__ gout = out + ((long long)b * NW + NWL * g) * 258;
    for (int idx = tid; idx < CNT; idx += THREADS) gout[idx] = sm[idx];
}

}  // namespace

extern "C" void kernel_launch(void* const* d_in, const int* in_sizes, int n_in,
                              void* d_out, int out_size) {
    const float* path = (const float*)d_in[0];
    float* out = (float*)d_out;
    fused_kernel<<<BATCH * GROUPS, THREADS>>>(path, out);
}

// round 13
// speedup vs baseline: 3.7823x; 3.7823x over previous
#include <cuda_runtime.h>

// Fused depth-3 sliding-window path signature (Chen chunk factorization).
// Best-known configuration (R10) + deeper scan unroll + vectorized copy-out.
// B=256, L=2048, C=6, WIN=64, STRIDE=32 -> 63 windows / batch.
// Grid = 1792 blocks (batch = blk/7, group g = blk%7) x 64 threads.
// Scan state: s1, T2 = 3*(2*s2), S3 = 6*s3. coef_j = a*d_j + T2[j] (1 FMA).
// dx staged as 3 float2 rows -> 3 LDS.64 + 1 LDS.32 per scan step.
// Output: combine -> regs -> smem [wl][258] -> float2-coalesced copy to global.

namespace {

constexpr int BATCH   = 256;
constexpr int LEN     = 2048;
constexpr int CH      = 6;
constexpr int NW      = 63;
constexpr int GROUPS  = 7;
constexpr int THREADS = 64;
constexpr int NCHUNKL = 10;               // chunks per block (1 overlap)
constexpr int NWL     = 9;                // windows per block (7*9 = 63 exact)
constexpr int NDXL    = 320;              // staged increments per block
constexpr int SROWD2  = 331;              // float2 row stride (320+10 pad, odd)
constexpr int NLANE   = NCHUNKL * CH;     // 60 scan lanes
constexpr int SCOL    = 61;               // sig column stride
constexpr int SM_FLOATS = 43 * SCOL;      // 2623 >= max(3*331*2=1986, 9*258=2322)

__global__ __launch_bounds__(THREADS, 14)
void fused_kernel(const float* __restrict__ path, float* __restrict__ out) {
    __shared__ __align__(16) float sm[SM_FLOATS];
    float2* __restrict__ s_dx2 = reinterpret_cast<float2*>(sm); // [3][SROWD2]
    float*  __restrict__ s_sig = sm;                            // [43][SCOL]

    const int tid = threadIdx.x;
    const int b   = blockIdx.x / GROUPS;
    const int g   = blockIdx.x - b * GROUPS;
    const int l0  = g * (NWL * 32);                 // 288 * g
    const float2* __restrict__ rowv =
        reinterpret_cast<const float2*>(path + (long long)b * (LEN * CH));
    // rowv[l*3 + pr] = channels (2pr, 2pr+1) at time l.

    // ---- stage increments as float2 (zero-fill global l >= 2047) ----
    for (int idx = tid; idx < NDXL * 3; idx += THREADS) {
        const int l  = idx / 3;
        const int pr = idx - l * 3;
        float2 d2 = make_float2(0.0f, 0.0f);
        const int gl = l0 + l;
        if (gl < LEN - 1) {
            const float2 v0 = rowv[gl * 3 + pr];
            const float2 v1 = rowv[gl * 3 + 3 + pr];
            d2.x = v1.x - v0.x;
            d2.y = v1.y - v0.y;
        }
        s_dx2[pr * SROWD2 + l + (l >> 5)] = d2;
    }
    __syncthreads();

    const int mc = tid / CH;       // local chunk 0..9 (tid>=60: idle lanes)
    const int i  = tid - mc * CH;  // leading channel
    const bool scan_lane = (tid < NLANE);

    float s1 = 0.0f;
    float T2[6];                   // 3 * S2  (S2 = 2*s2)
    float S3[6][6];                // 6 * s3
#pragma unroll
    for (int j = 0; j < 6; ++j) {
        T2[j] = 0.0f;
#pragma unroll
        for (int k = 0; k < 6; ++k) S3[j][k] = 0.0f;
    }

    if (scan_lane) {
        const int base = 33 * mc;  // padded float2 offset of local l = 32*mc
        const float* __restrict__ rowi = sm + 2 * (i >> 1) * SROWD2 + (i & 1);

#pragma unroll 8
        for (int t = 0; t < 32; ++t) {
            const int off = base + t;            // t<32: no extra pad term
            const float2 d01 = s_dx2[0 * SROWD2 + off];
            const float2 d23 = s_dx2[1 * SROWD2 + off];
            const float2 d45 = s_dx2[2 * SROWD2 + off];
            const float di = rowi[2 * off];

            const float a   = fmaf(3.0f, s1, di);          // di + 3 s1 (old s1)
            const float b23 = fmaf(6.0f, s1, 3.0f * di);   // 3*(di + 2 s1)

            const float d[6] = {d01.x, d01.y, d23.x, d23.y, d45.x, d45.y};

            float coef[6];                                  // uses old T2
#pragma unroll
            for (int j = 0; j < 6; ++j) coef[j] = fmaf(a, d[j], T2[j]);

#pragma unroll
            for (int j = 0; j < 6; ++j)
#pragma unroll
                for (int k = 0; k < 6; ++k)
                    S3[j][k] = fmaf(coef[j], d[k], S3[j][k]);

#pragma unroll
            for (int j = 0; j < 6; ++j) T2[j] = fmaf(b23, d[j], T2[j]);
            s1 += di;
        }
    }

    // ---- snapshot d_last for local window wl = mc (local l' = 32mc+63) ----
    float dc[6];
    {
        const int off = 33 * mc + 64;            // (32mc+63) + ((32mc+63)>>5)
        const bool cwn = (mc < NWL);
        float2 c01 = make_float2(0.0f, 0.0f), c23 = c01, c45 = c01;
        if (cwn) {
            c01 = s_dx2[0 * SROWD2 + off];
            c23 = s_dx2[1 * SROWD2 + off];
            c45 = s_dx2[2 * SROWD2 + off];
        }
        dc[0] = c01.x; dc[1] = c01.y; dc[2] = c23.x;
        dc[3] = c23.y; dc[4] = c45.x; dc[5] = c45.y;
    }
    __syncthreads();   // all dx reads done before s_sig overwrites

    // ---- publish chunk state: S2 = T2/3, column = tid ----
    if (scan_lane) {
        s_sig[tid] = s1;
        const float third = 1.0f / 3.0f;
#pragma unroll
        for (int j = 0; j < 6; ++j) s_sig[(1 + j) * SCOL + tid] = T2[j] * third;
#pragma unroll
        for (int j = 0; j < 6; ++j)
#pragma unroll
            for (int k = 0; k < 6; ++k)
                s_sig[(7 + j * 6 + k) * SCOL + tid] = S3[j][k];
    }
    __syncthreads();

    // ---- combine into registers: window w = 9g + mc ----
    const bool cw = (mc < NWL);    // w = 9g + mc <= 9*6+8 = 62 < NW always

    float r1 = 0.0f, r2[6], r3[6][6];
    if (cw) {
        const int ca  = tid;               // A_w lane i
        const int cb0 = (mc + 1) * CH;     // A_{w+1} lane base
        const int cbi = cb0 + i;

        const float a1 = s_sig[ca];
        float b1[6];
#pragma unroll
        for (int j = 0; j < 6; ++j) b1[j] = s_sig[cb0 + j];

        const float m1 = a1 + b1[i];

        // M2 row i (2x): M2[j] = A2[i][j] + B2[i][j] + 2 a1 b1[j]
        float A2r[6], M2[6];
#pragma unroll
        for (int j = 0; j < 6; ++j) {
            A2r[j] = s_sig[(1 + j) * SCOL + ca];
            M2[j]  = A2r[j] + s_sig[(1 + j) * SCOL + cbi] + 2.0f * a1 * b1[j];
        }

        r1 = m1 - dc[i];

        const float c2 = dc[i] - 2.0f * m1;
#pragma unroll
        for (int j = 0; j < 6; ++j) r2[j] = fmaf(c2, dc[j], M2[j]);

        const float t3a1 = 3.0f * a1;
        const float c3   = 3.0f * m1 - dc[i];
#pragma unroll
        for (int j = 0; j < 6; ++j) {
            const float a2b  = 3.0f * A2r[j];
            const float coef = fmaf(c3, dc[j], -3.0f * M2[j]);
#pragma unroll
            for (int k = 0; k < 6; ++k) {
                float v = s_sig[(7 + j * 6 + k) * SCOL + ca]
                        + s_sig[(7 + j * 6 + k) * SCOL + cbi];
                v = fmaf(a2b, b1[k], v);
                v = fmaf(t3a1, s_sig[(1 + k) * SCOL + cb0 + j], v);
                r3[j][k] = fmaf(coef, dc[k], v);
            }
        }
    }
    __syncthreads();   // all s_sig reads done before output staging overwrites

    // ---- stage output in smem as [wl][258] ----
    if (cw) {
        float* __restrict__ so = sm + mc * 258;
        so[i] = r1;
#pragma unroll
        for (int j = 0; j < 6; ++j) so[6 + i * 6 + j] = r2[j];
#pragma unroll
        for (int j = 0; j < 6; ++j)
#pragma unroll
            for (int k = 0; k < 6; ++k) so[42 + i * 36 + j * 6 + k] = r3[j][k];
    }
    __syncthreads();

    // ---- float2-coalesced copy to global (9*258 = 2322 floats = 1161 f2) ----
    constexpr int CNT2 = NWL * 258 / 2;  // 1161
    const float2* __restrict__ ssrc = reinterpret_cast<const float2*>(sm);
    float2* __restrict__ gout = reinterpret_cast<float2*>(
        out + ((long long)b * NW + NWL * g) * 258);
    for (int idx = tid; idx < CNT2; idx += THREADS) gout[idx] = ssrc[idx];
}

}  // namespace

extern "C" void kernel_launch(void* const* d_in, const int* in_sizes, int n_in,
                              void* d_out, int out_size) {
    const float* path = (const float*)d_in[0];
    float* out = (float*)d_out;
    fused_kernel<<<BATCH * GROUPS, THREADS>>>(path, out);
}